// round 1
// baseline (speedup 1.0000x reference)
#include <cuda_runtime.h>
#include <math.h>

#define N_IN  32768
#define KC    4096
#define DIM   256

// ---- scratch (device globals; no allocation allowed) ----
__device__ float  g_A[N_IN];        // row norms |x_i|^2
__device__ float  g_B[KC];          // code norms |e_k|^2
__device__ int    g_argmin[N_IN];
__device__ int    g_counts[KC];
__device__ double g_partial[512];   // per-block loss partial sums

// ---------------------------------------------------------------------------
// init: zero counts
// ---------------------------------------------------------------------------
__global__ void init_kernel() {
    int t = blockIdx.x * blockDim.x + threadIdx.x;
    if (t < KC) g_counts[t] = 0;
}

// ---------------------------------------------------------------------------
// row norms of x: warp per row, lane sums elems lane, lane+32, ... (fixed order)
// ---------------------------------------------------------------------------
__global__ void norms_x_kernel(const float* __restrict__ x) {
    int warp = (blockIdx.x * blockDim.x + threadIdx.x) >> 5;
    int lane = threadIdx.x & 31;
    if (warp >= N_IN) return;
    const float* r = x + (size_t)warp * DIM;
    float s = 0.f;
    #pragma unroll
    for (int i = 0; i < DIM / 32; i++) {
        float v = r[lane + i * 32];
        s = __fadd_rn(s, __fmul_rn(v, v));
    }
    #pragma unroll
    for (int o = 16; o > 0; o >>= 1)
        s = __fadd_rn(s, __shfl_xor_sync(0xffffffffu, s, o));
    if (lane == 0) g_A[warp] = s;
}

__global__ void norms_w_kernel(const float* __restrict__ w) {
    int warp = (blockIdx.x * blockDim.x + threadIdx.x) >> 5;
    int lane = threadIdx.x & 31;
    if (warp >= KC) return;
    const float* r = w + (size_t)warp * DIM;
    float s = 0.f;
    #pragma unroll
    for (int i = 0; i < DIM / 32; i++) {
        float v = r[lane + i * 32];
        s = __fadd_rn(s, __fmul_rn(v, v));
    }
    #pragma unroll
    for (int o = 16; o > 0; o >>= 1)
        s = __fadd_rn(s, __shfl_xor_sync(0xffffffffu, s, o));
    if (lane == 0) g_B[warp] = s;
}

// ---------------------------------------------------------------------------
// zero encodings region (float2: region base is 8-byte but not 16-byte aligned)
// ---------------------------------------------------------------------------
__global__ void zero_enc_kernel(float2* __restrict__ enc2, long long n2) {
    long long stride = (long long)gridDim.x * blockDim.x;
    for (long long i = blockIdx.x * (long long)blockDim.x + threadIdx.x;
         i < n2; i += stride)
        enc2[i] = make_float2(0.f, 0.f);
}

// ---------------------------------------------------------------------------
// fused distance GEMM + argmin.
// CTA: 64 rows x 4096 cols; col tiles of 128, K(depth)-tiles of 32.
// threads 256 = 16x16, each thread 4 rows x 8 cols of accumulators.
// distance replicates reference rounding: v = fl(fl(A+B) - 2*d).
// ---------------------------------------------------------------------------
__global__ __launch_bounds__(256)
void gemm_argmin_kernel(const float* __restrict__ x, const float* __restrict__ w) {
    __shared__ float As[32][65];    // [k][row]
    __shared__ float Bs[32][132];   // [k][col]
    __shared__ float redv[64][17];
    __shared__ int   redi[64][17];

    const int tid = threadIdx.x;
    const int ty = tid >> 4;        // 0..15
    const int tx = tid & 15;        // 0..15
    const int row0 = blockIdx.x * 64;

    float bestv[4];
    int   besti[4];
    float Arow[4];
    #pragma unroll
    for (int i = 0; i < 4; i++) {
        bestv[i] = 3.4e38f;
        besti[i] = 0;
        Arow[i]  = g_A[row0 + ty * 4 + i];
    }

    for (int nc = 0; nc < KC / 128; nc++) {
        const int col0 = nc * 128;
        float acc[4][8];
        #pragma unroll
        for (int i = 0; i < 4; i++)
            #pragma unroll
            for (int j = 0; j < 8; j++) acc[i][j] = 0.f;

        for (int dk = 0; dk < DIM; dk += 32) {
            // load x tile 64x32 (512 float4, 2 per thread), transposed into As
            #pragma unroll
            for (int l = 0; l < 2; l++) {
                int li = tid + l * 256;
                int r = li >> 3, c4 = li & 7;
                float4 v = *(const float4*)(x + (size_t)(row0 + r) * DIM + dk + c4 * 4);
                As[c4 * 4 + 0][r] = v.x;
                As[c4 * 4 + 1][r] = v.y;
                As[c4 * 4 + 2][r] = v.z;
                As[c4 * 4 + 3][r] = v.w;
            }
            // load w tile 128x32 (1024 float4, 4 per thread), transposed into Bs
            #pragma unroll
            for (int l = 0; l < 4; l++) {
                int li = tid + l * 256;
                int r = li >> 3, c4 = li & 7;
                float4 v = *(const float4*)(w + (size_t)(col0 + r) * DIM + dk + c4 * 4);
                Bs[c4 * 4 + 0][r] = v.x;
                Bs[c4 * 4 + 1][r] = v.y;
                Bs[c4 * 4 + 2][r] = v.z;
                Bs[c4 * 4 + 3][r] = v.w;
            }
            __syncthreads();
            #pragma unroll
            for (int kk = 0; kk < 32; kk++) {
                float a[4], b[8];
                #pragma unroll
                for (int i = 0; i < 4; i++) a[i] = As[kk][ty * 4 + i];
                #pragma unroll
                for (int j = 0; j < 8; j++) b[j] = Bs[kk][tx * 8 + j];
                #pragma unroll
                for (int i = 0; i < 4; i++)
                    #pragma unroll
                    for (int j = 0; j < 8; j++)
                        acc[i][j] = fmaf(a[i], b[j], acc[i][j]);
            }
            __syncthreads();
        }

        // epilogue for this col tile: replicate fl(fl(A+B) - 2d), track argmin
        #pragma unroll
        for (int j = 0; j < 8; j++) {
            int col = col0 + tx * 8 + j;
            float Bc = g_B[col];
            #pragma unroll
            for (int i = 0; i < 4; i++) {
                float u = __fadd_rn(Arow[i], Bc);
                float v = __fsub_rn(u, __fmul_rn(2.0f, acc[i][j]));
                if (v < bestv[i]) { bestv[i] = v; besti[i] = col; }
            }
        }
    }

    #pragma unroll
    for (int i = 0; i < 4; i++) {
        redv[ty * 4 + i][tx] = bestv[i];
        redi[ty * 4 + i][tx] = besti[i];
    }
    __syncthreads();
    if (tid < 64) {
        float bv = redv[tid][0];
        int   bi = redi[tid][0];
        #pragma unroll
        for (int t = 1; t < 16; t++) {
            float v = redv[tid][t];
            int   ii = redi[tid][t];
            if (v < bv || (v == bv && ii < bi)) { bv = v; bi = ii; }
        }
        g_argmin[row0 + tid] = bi;
    }
}

// ---------------------------------------------------------------------------
// epilogue: quantized_st (scalar stores, base misaligned), one-hot scatter,
// counts, per-block loss partials (deterministic).
// block: 64 rows, 4 threads/row, interleaved element mapping for coalescing.
// ---------------------------------------------------------------------------
__global__ __launch_bounds__(256)
void epilogue_kernel(const float* __restrict__ x, const float* __restrict__ w,
                     float* __restrict__ out_qst, float* __restrict__ out_enc) {
    __shared__ double sred[256];
    const int tid = threadIdx.x;
    const int rowLocal = tid >> 2;
    const int sub = tid & 3;
    const int row = blockIdx.x * 64 + rowLocal;
    const int idx = g_argmin[row];

    const float* wr = w + (size_t)idx * DIM;
    const float* xr = x + (size_t)row * DIM;
    float* qr = out_qst + (size_t)row * DIM;

    double ls = 0.0;
    #pragma unroll 8
    for (int u = 0; u < DIM / 4; u++) {
        int e = u * 4 + sub;
        float wv = wr[e];
        float xv = xr[e];
        float dlt = __fsub_rn(wv, xv);          // fl(q - x)
        qr[e] = __fadd_rn(xv, dlt);             // fl(x + fl(q-x))  (STE value)
        float t = __fmul_rn(dlt, dlt);
        ls += (double)t;
    }
    if (sub == 0) {
        out_enc[(size_t)row * KC + idx] = 1.0f;
        atomicAdd(&g_counts[idx], 1);
    }
    sred[tid] = ls;
    __syncthreads();
    #pragma unroll
    for (int s = 128; s > 0; s >>= 1) {
        if (tid < s) sred[tid] += sred[tid + s];
        __syncthreads();
    }
    if (tid == 0) g_partial[blockIdx.x] = sred[0];
}

// ---------------------------------------------------------------------------
// finalize: loss scalar + perplexity scalar (deterministic fixed-order reduces)
// ---------------------------------------------------------------------------
__global__ __launch_bounds__(256)
void finalize_kernel(float* __restrict__ out_loss, float* __restrict__ out_perp) {
    __shared__ double sred[256];
    const int tid = threadIdx.x;

    // loss: sum 512 partials
    double s = g_partial[tid] + g_partial[tid + 256];
    sred[tid] = s;
    __syncthreads();
    #pragma unroll
    for (int st = 128; st > 0; st >>= 1) {
        if (tid < st) sred[tid] += sred[tid + st];
        __syncthreads();
    }
    if (tid == 0) {
        double total = sred[0];
        float m = (float)(total / (double)((long long)N_IN * DIM));
        float loss = __fadd_rn(m, __fmul_rn(0.25f, m));   // q_loss + 0.25*e_loss
        *out_loss = loss;
    }
    __syncthreads();

    // perplexity from counts
    double ps = 0.0;
    #pragma unroll
    for (int i = 0; i < KC / 256; i++) {
        int k = tid + i * 256;
        float p = (float)g_counts[k] * (1.0f / (float)N_IN);
        float term = p * logf(__fadd_rn(p, 1e-10f));
        ps += (double)term;
    }
    sred[tid] = ps;
    __syncthreads();
    #pragma unroll
    for (int st = 128; st > 0; st >>= 1) {
        if (tid < st) sred[tid] += sred[tid + st];
        __syncthreads();
    }
    if (tid == 0) {
        float perp = expf((float)(-sred[0]));
        *out_perp = perp;
    }
}

// ---------------------------------------------------------------------------
extern "C" void kernel_launch(void* const* d_in, const int* in_sizes, int n_in,
                              void* d_out, int out_size) {
    // identify inputs by size (inputs: 8388608, weight: 1048576)
    const float* x = (const float*)d_in[0];
    const float* w = (const float*)d_in[1];
    if (n_in >= 2 && in_sizes[0] == KC * DIM && in_sizes[1] == N_IN * DIM) {
        x = (const float*)d_in[1];
        w = (const float*)d_in[0];
    }

    float* out = (float*)d_out;
    // layout: [loss(1), quantized_st(N*D), perplexity(1), encodings(N*K)]
    float* out_loss = out;
    float* out_qst  = out + 1;
    float* out_perp = out + 1 + (size_t)N_IN * DIM;
    float* out_enc  = out + 2 + (size_t)N_IN * DIM;

    init_kernel<<<(KC + 255) / 256, 256>>>();
    norms_x_kernel<<<N_IN / 8, 256>>>(x);       // 8 warps/block
    norms_w_kernel<<<KC / 8, 256>>>(w);

    long long n2 = (long long)N_IN * KC / 2;    // float2 count
    zero_enc_kernel<<<8192, 256>>>((float2*)out_enc, n2);

    gemm_argmin_kernel<<<N_IN / 64, 256>>>(x, w);
    epilogue_kernel<<<N_IN / 64, 256>>>(x, w, out_qst, out_enc);
    finalize_kernel<<<1, 256>>>(out_loss, out_perp);
}

// round 4
// speedup vs baseline: 3.1604x; 3.1604x over previous
#include <cuda_runtime.h>
#include <cuda_bf16.h>
#include <math.h>
#include <stdint.h>

#define N_IN  32768
#define KC    4096
#define DIM   256
#define M_TILE 128
#define NT_COLS 128
#define K_CH   64                        // bf16 elems per chunk = 128B per row
#define N_NT   (KC / NT_COLS)            // 32
#define CH_PER_NT (DIM / K_CH)           // 4
#define N_CHUNKS (N_NT * CH_PER_NT)      // 128
#define STAGES 4
#define STG_BYTES (M_TILE * 128)         // 16KB per operand stage
#define EPS 5e-4f

// ---- scratch (device globals; no allocation allowed) ----
__device__ __nv_bfloat16 g_Xbf[(size_t)N_IN * DIM];   // 16MB
__device__ __nv_bfloat16 g_Wbf[(size_t)KC   * DIM];   // 2MB
__device__ float  g_A[N_IN];
__device__ float  g_B[KC];
__device__ int    g_argmin[N_IN];
__device__ int    g_counts[KC];
__device__ double g_partial[512];

// ===========================================================================
// helpers
// ===========================================================================
__device__ __forceinline__ uint32_t smem_u32(const void* p) {
    uint32_t a;
    asm("{ .reg .u64 t; cvta.to.shared.u64 t, %1; cvt.u32.u64 %0, t; }" : "=r"(a) : "l"(p));
    return a;
}
#define CP_ASYNC16(dst, src) \
    asm volatile("cp.async.cg.shared.global [%0], [%1], 16;" :: "r"(dst), "l"(src) : "memory")
#define CP_COMMIT() asm volatile("cp.async.commit_group;" ::: "memory")

__device__ __forceinline__ uint32_t swz(uint32_t off) { return off ^ ((off >> 3) & 0x70); }

__device__ __forceinline__ void ldsm4(uint32_t* r, uint32_t addr) {
    asm volatile("ldmatrix.sync.aligned.m8n8.x4.shared.b16 {%0,%1,%2,%3}, [%4];"
        : "=r"(r[0]), "=r"(r[1]), "=r"(r[2]), "=r"(r[3]) : "r"(addr));
}
__device__ __forceinline__ void mma_bf16(float* c, const uint32_t* a, uint32_t b0, uint32_t b1) {
    asm volatile("mma.sync.aligned.m16n8k16.row.col.f32.bf16.bf16.f32 "
        "{%0,%1,%2,%3}, {%4,%5,%6,%7}, {%8,%9}, {%0,%1,%2,%3};"
        : "+f"(c[0]), "+f"(c[1]), "+f"(c[2]), "+f"(c[3])
        : "r"(a[0]), "r"(a[1]), "r"(a[2]), "r"(a[3]), "r"(b0), "r"(b1));
}
__device__ __forceinline__ bool lex_less(float v1, int i1, float v2, int i2) {
    return v1 < v2 || (v1 == v2 && i1 < i2);
}

// ===========================================================================
// small kernels
// ===========================================================================
__global__ void init_kernel() {
    int t = blockIdx.x * blockDim.x + threadIdx.x;
    if (t < KC) g_counts[t] = 0;
}

__global__ void cvt_kernel(const float* __restrict__ src, __nv_bfloat16* __restrict__ dst, int n) {
    int stride = gridDim.x * blockDim.x;
    for (int i = blockIdx.x * blockDim.x + threadIdx.x; i < n; i += stride)
        dst[i] = __float2bfloat16(src[i]);
}

__global__ void norms_x_kernel(const float* __restrict__ x) {
    int warp = (blockIdx.x * blockDim.x + threadIdx.x) >> 5;
    int lane = threadIdx.x & 31;
    if (warp >= N_IN) return;
    const float* r = x + (size_t)warp * DIM;
    float s = 0.f;
    #pragma unroll
    for (int i = 0; i < DIM / 32; i++) {
        float v = r[lane + i * 32];
        s = __fadd_rn(s, __fmul_rn(v, v));
    }
    #pragma unroll
    for (int o = 16; o > 0; o >>= 1)
        s = __fadd_rn(s, __shfl_xor_sync(0xffffffffu, s, o));
    if (lane == 0) g_A[warp] = s;
}

__global__ void norms_w_kernel(const float* __restrict__ w) {
    int warp = (blockIdx.x * blockDim.x + threadIdx.x) >> 5;
    int lane = threadIdx.x & 31;
    if (warp >= KC) return;
    const float* r = w + (size_t)warp * DIM;
    float s = 0.f;
    #pragma unroll
    for (int i = 0; i < DIM / 32; i++) {
        float v = r[lane + i * 32];
        s = __fadd_rn(s, __fmul_rn(v, v));
    }
    #pragma unroll
    for (int o = 16; o > 0; o >>= 1)
        s = __fadd_rn(s, __shfl_xor_sync(0xffffffffu, s, o));
    if (lane == 0) g_B[warp] = s;
}

// zero encodings; region byte offset is 8 mod 16 -> scalar head/tail + float4 body
__global__ void zero_enc_kernel(float* __restrict__ enc) {
    const long long n4 = ((long long)N_IN * KC - 4) / 4;
    float4* v4 = (float4*)(enc + 2);
    long long stride = (long long)gridDim.x * blockDim.x;
    long long i0 = blockIdx.x * (long long)blockDim.x + threadIdx.x;
    float4 z = make_float4(0.f, 0.f, 0.f, 0.f);
    for (long long i = i0; i < n4; i += stride) v4[i] = z;
    if (i0 == 0) {
        enc[0] = 0.f; enc[1] = 0.f;
        enc[(long long)N_IN * KC - 2] = 0.f;
        enc[(long long)N_IN * KC - 1] = 0.f;
    }
}

// ===========================================================================
// bf16 mma.sync distance GEMM + top-3 shortlist + in-kernel exact fp32 refine
// CTA: 128 rows x (32 N-tiles of 128 cols); K=256 in chunks of 64 bf16.
// 8 warps = 4(m) x 2(n); warp tile 32x64.
// ===========================================================================
__global__ __launch_bounds__(256, 1)
void gemm_mma_kernel(const float* __restrict__ x, const float* __restrict__ w) {
    extern __shared__ char smem[];
    const uint32_t sbase = smem_u32(smem);
    const int tid  = threadIdx.x;
    const int wid  = tid >> 5;
    const int lane = tid & 31;
    const int warp_m = wid & 3;
    const int warp_n = wid >> 2;
    const int row0 = blockIdx.x * M_TILE;

    const uint32_t A_OFF = 0;
    const uint32_t B_OFF = STAGES * STG_BYTES;   // 64KB

    // ldmatrix per-lane geometry (canonical x4 non-trans)
    const int a_row_l = (((lane >> 3) & 1) << 3) + (lane & 7);  // row within 16
    const int a_seg   = (lane >> 4) << 4;                       // byte seg {0,16}
    const int b_n_l   = ((lane >> 4) << 3) + (lane & 7);        // n within 16
    const int b_seg   = ((lane >> 3) & 1) << 4;                 // byte seg {0,16}

    float acc[2][8][4];
    #pragma unroll
    for (int mi = 0; mi < 2; mi++)
        #pragma unroll
        for (int ni = 0; ni < 8; ni++)
            #pragma unroll
            for (int q = 0; q < 4; q++) acc[mi][ni][q] = 0.f;

    // top-3 per local row (4 local rows per thread), lex-sorted ascending
    float cv[4][3];
    int   ci[4][3];
    float Arow[4];
    #pragma unroll
    for (int lr = 0; lr < 4; lr++) {
        cv[lr][0] = cv[lr][1] = cv[lr][2] = 3.4e38f;
        ci[lr][0] = ci[lr][1] = ci[lr][2] = 0x7fffffff;
        int mi = lr >> 1, h = lr & 1;
        Arow[lr] = g_A[row0 + warp_m * 32 + mi * 16 + h * 8 + (lane >> 2)];
    }

    const __nv_bfloat16* xs = g_Xbf + (size_t)row0 * DIM;

    #pragma unroll 1
    for (int c = 0; c < N_CHUNKS + 2; c++) {
        if (c < N_CHUNKS) {
            const int s  = c & 3;
            const int nt = c >> 2;
            const int kc = c & 3;
            const uint32_t Ab = sbase + A_OFF + s * STG_BYTES;
            const __nv_bfloat16* ga = xs + kc * K_CH;
            #pragma unroll
            for (int i = 0; i < 4; i++) {
                int id = tid + i * 256;
                int r = id >> 3, k8 = id & 7;
                CP_ASYNC16(Ab + swz(r * 128 + k8 * 16), ga + (size_t)r * DIM + k8 * 8);
            }
            const uint32_t Bb = sbase + B_OFF + s * STG_BYTES;
            const __nv_bfloat16* gb = g_Wbf + (size_t)(nt * NT_COLS) * DIM + kc * K_CH;
            #pragma unroll
            for (int i = 0; i < 4; i++) {
                int id = tid + i * 256;
                int r = id >> 3, k8 = id & 7;
                CP_ASYNC16(Bb + swz(r * 128 + k8 * 16), gb + (size_t)r * DIM + k8 * 8);
            }
            CP_COMMIT();
        }
        if (c >= 2) {
            if (c < N_CHUNKS)           asm volatile("cp.async.wait_group 2;" ::: "memory");
            else if (c == N_CHUNKS)     asm volatile("cp.async.wait_group 1;" ::: "memory");
            else                        asm volatile("cp.async.wait_group 0;" ::: "memory");
            __syncthreads();

            const int cm  = c - 2;
            const int sm_ = cm & 3;
            const uint32_t Ab = sbase + A_OFF + sm_ * STG_BYTES;
            const uint32_t Bb = sbase + B_OFF + sm_ * STG_BYTES;

            #pragma unroll
            for (int k16 = 0; k16 < 4; k16++) {
                const int kb = k16 * 32;              // byte base in 128B row
                uint32_t af[2][4];
                #pragma unroll
                for (int mi = 0; mi < 2; mi++)
                    ldsm4(af[mi], Ab + swz((warp_m * 32 + mi * 16 + a_row_l) * 128
                                           + kb + a_seg));
                uint32_t bf[4][4];
                #pragma unroll
                for (int p = 0; p < 4; p++)
                    ldsm4(bf[p], Bb + swz((warp_n * 64 + p * 16 + b_n_l) * 128
                                          + kb + b_seg));
                #pragma unroll
                for (int mi = 0; mi < 2; mi++)
                    #pragma unroll
                    for (int ni = 0; ni < 8; ni++)
                        mma_bf16(acc[mi][ni], af[mi],
                                 bf[ni >> 1][(ni & 1) * 2], bf[ni >> 1][(ni & 1) * 2 + 1]);
            }

            if ((cm & 3) == 3) {
                // N-tile finished: approx distances, maintain top-3 shortlist
                const int nt = cm >> 2;
                const int colbase = nt * NT_COLS + warp_n * 64;
                #pragma unroll
                for (int mi = 0; mi < 2; mi++)
                    #pragma unroll
                    for (int h = 0; h < 2; h++) {
                        const int lr = mi * 2 + h;
                        #pragma unroll
                        for (int ni = 0; ni < 8; ni++)
                            #pragma unroll
                            for (int cc = 0; cc < 2; cc++) {
                                const int col = colbase + ni * 8 + 2 * (lane & 3) + cc;
                                float d = acc[mi][ni][h * 2 + cc];
                                float u = __fadd_rn(Arow[lr], g_B[col]);
                                float v = __fsub_rn(u, __fmul_rn(2.0f, d));
                                if (lex_less(v, col, cv[lr][2], ci[lr][2])) {
                                    cv[lr][2] = v; ci[lr][2] = col;
                                    if (lex_less(cv[lr][2], ci[lr][2], cv[lr][1], ci[lr][1])) {
                                        float tv = cv[lr][1]; int ti = ci[lr][1];
                                        cv[lr][1] = cv[lr][2]; ci[lr][1] = ci[lr][2];
                                        cv[lr][2] = tv; ci[lr][2] = ti;
                                    }
                                    if (lex_less(cv[lr][1], ci[lr][1], cv[lr][0], ci[lr][0])) {
                                        float tv = cv[lr][0]; int ti = ci[lr][0];
                                        cv[lr][0] = cv[lr][1]; ci[lr][0] = ci[lr][1];
                                        cv[lr][1] = tv; ci[lr][1] = ti;
                                    }
                                }
                                acc[mi][ni][h * 2 + cc] = 0.f;
                            }
                    }
            }
        }
    }

    // gather shortlist to smem: 128 rows x 24 entries
    __syncthreads();
    float* redv = (float*)smem;                    // 128*24*4 = 12KB
    int*   redi = (int*)(smem + 128 * 24 * 4);     // 12KB
    #pragma unroll
    for (int lr = 0; lr < 4; lr++) {
        int mi = lr >> 1, h = lr & 1;
        const int row = warp_m * 32 + mi * 16 + h * 8 + (lane >> 2);
        const int slot = (warp_n * 4 + (lane & 3)) * 3;
        #pragma unroll
        for (int j = 0; j < 3; j++) {
            redv[row * 24 + slot + j] = cv[lr][j];
            redi[row * 24 + slot + j] = ci[lr][j];
        }
    }
    __syncthreads();

    // exact fp32 refine: one thread per row
    if (tid < 128) {
        const int row = row0 + tid;
        float gmin = 3.4e38f;
        #pragma unroll
        for (int j = 0; j < 24; j++)
            gmin = fminf(gmin, redv[tid * 24 + j]);
        const float thresh = gmin + EPS;
        const float Ar = g_A[row];
        const float* xr = x + (size_t)row * DIM;

        float bestv = 3.4e38f;
        int   besti = 0x7fffffff;
        for (int j = 0; j < 24; j++) {
            float va = redv[tid * 24 + j];
            int   col = redi[tid * 24 + j];
            if (va > thresh || col == 0x7fffffff) continue;
            const float* wr = w + (size_t)col * DIM;
            float dot = 0.f;
            #pragma unroll 8
            for (int k = 0; k < DIM; k++)
                dot = fmaf(xr[k], __ldg(wr + k), dot);
            float u = __fadd_rn(Ar, g_B[col]);
            float ve = __fsub_rn(u, __fmul_rn(2.0f, dot));
            if (lex_less(ve, col, bestv, besti)) { bestv = ve; besti = col; }
        }
        g_argmin[row] = besti;
    }
}

// ===========================================================================
// epilogue + finalize
// ===========================================================================
__global__ __launch_bounds__(256)
void epilogue_kernel(const float* __restrict__ x, const float* __restrict__ w,
                     float* __restrict__ out_qst, float* __restrict__ out_enc) {
    __shared__ double sred[256];
    const int tid = threadIdx.x;
    const int rowLocal = tid >> 2;
    const int sub = tid & 3;
    const int row = blockIdx.x * 64 + rowLocal;
    const int idx = g_argmin[row];

    const float* wr = w + (size_t)idx * DIM;
    const float* xr = x + (size_t)row * DIM;
    float* qr = out_qst + (size_t)row * DIM;

    double ls = 0.0;
    #pragma unroll 8
    for (int u = 0; u < DIM / 4; u++) {
        int e = u * 4 + sub;
        float wv = wr[e];
        float xv = xr[e];
        float dlt = __fsub_rn(wv, xv);
        qr[e] = __fadd_rn(xv, dlt);
        float t = __fmul_rn(dlt, dlt);
        ls += (double)t;
    }
    if (sub == 0) {
        out_enc[(size_t)row * KC + idx] = 1.0f;
        atomicAdd(&g_counts[idx], 1);
    }
    sred[tid] = ls;
    __syncthreads();
    #pragma unroll
    for (int s = 128; s > 0; s >>= 1) {
        if (tid < s) sred[tid] += sred[tid + s];
        __syncthreads();
    }
    if (tid == 0) g_partial[blockIdx.x] = sred[0];
}

__global__ __launch_bounds__(256)
void finalize_kernel(float* __restrict__ out_loss, float* __restrict__ out_perp) {
    __shared__ double sred[256];
    const int tid = threadIdx.x;

    double s = g_partial[tid] + g_partial[tid + 256];
    sred[tid] = s;
    __syncthreads();
    #pragma unroll
    for (int st = 128; st > 0; st >>= 1) {
        if (tid < st) sred[tid] += sred[tid + st];
        __syncthreads();
    }
    if (tid == 0) {
        double total = sred[0];
        float m = (float)(total / (double)((long long)N_IN * DIM));
        *out_loss = __fadd_rn(m, __fmul_rn(0.25f, m));
    }
    __syncthreads();

    double ps = 0.0;
    #pragma unroll
    for (int i = 0; i < KC / 256; i++) {
        int k = tid + i * 256;
        float p = (float)g_counts[k] * (1.0f / (float)N_IN);
        float term = p * logf(__fadd_rn(p, 1e-10f));
        ps += (double)term;
    }
    sred[tid] = ps;
    __syncthreads();
    #pragma unroll
    for (int st = 128; st > 0; st >>= 1) {
        if (tid < st) sred[tid] += sred[tid + st];
        __syncthreads();
    }
    if (tid == 0) *out_perp = expf((float)(-sred[0]));
}

// ===========================================================================
extern "C" void kernel_launch(void* const* d_in, const int* in_sizes, int n_in,
                              void* d_out, int out_size) {
    const float* x = (const float*)d_in[0];
    const float* w = (const float*)d_in[1];
    if (n_in >= 2 && in_sizes[0] == KC * DIM && in_sizes[1] == N_IN * DIM) {
        x = (const float*)d_in[1];
        w = (const float*)d_in[0];
    }

    float* out = (float*)d_out;
    float* out_loss = out;
    float* out_qst  = out + 1;
    float* out_perp = out + 1 + (size_t)N_IN * DIM;
    float* out_enc  = out + 2 + (size_t)N_IN * DIM;

    __nv_bfloat16* xbf = nullptr; __nv_bfloat16* wbf = nullptr;
    cudaGetSymbolAddress((void**)&xbf, g_Xbf);
    cudaGetSymbolAddress((void**)&wbf, g_Wbf);

    const int SMEM_BYTES = 2 * STAGES * STG_BYTES;   // 128KB
    cudaFuncSetAttribute(gemm_mma_kernel, cudaFuncAttributeMaxDynamicSharedMemorySize, SMEM_BYTES);

    init_kernel<<<(KC + 255) / 256, 256>>>();
    cvt_kernel<<<2048, 256>>>(x, xbf, N_IN * DIM);
    cvt_kernel<<<512, 256>>>(w, wbf, KC * DIM);
    norms_x_kernel<<<N_IN / 8, 256>>>(x);
    norms_w_kernel<<<KC / 8, 256>>>(w);
    zero_enc_kernel<<<8192, 256>>>(out_enc);

    gemm_mma_kernel<<<N_IN / M_TILE, 256, SMEM_BYTES>>>(x, w);

    epilogue_kernel<<<N_IN / 64, 256>>>(x, w, out_qst, out_enc);
    finalize_kernel<<<1, 256>>>(out_loss, out_perp);
}

// round 6
// speedup vs baseline: 3.9241x; 1.2417x over previous
#include <cuda_runtime.h>
#include <cuda_bf16.h>
#include <math.h>
#include <stdint.h>

#define N_IN  32768
#define KC    4096
#define DIM   256
#define M_TILE 128
#define NT_COLS 128
#define K_CH   64                        // bf16 elems per chunk = 128B per row
#define N_NT   (KC / NT_COLS)            // 32
#define CH_PER_NT (DIM / K_CH)           // 4
#define N_CHUNKS (N_NT * CH_PER_NT)      // 128
#define STAGES 3
#define STG_BYTES (M_TILE * 128)         // 16KB per operand stage
#define EPS 5e-4f

// ---- scratch (device globals; no allocation allowed) ----
__device__ __nv_bfloat16 g_Xbf[(size_t)N_IN * DIM];   // 16MB
__device__ __nv_bfloat16 g_Wbf[(size_t)KC   * DIM];   // 2MB
__device__ float  g_A[N_IN];
__device__ float  g_B[KC];
__device__ int    g_argmin[N_IN];
__device__ int    g_counts[KC];
__device__ double g_partial[512];

// ===========================================================================
// helpers
// ===========================================================================
__device__ __forceinline__ uint32_t smem_u32(const void* p) {
    uint32_t a;
    asm("{ .reg .u64 t; cvta.to.shared.u64 t, %1; cvt.u32.u64 %0, t; }" : "=r"(a) : "l"(p));
    return a;
}
#define CP_ASYNC16(dst, src) \
    asm volatile("cp.async.cg.shared.global [%0], [%1], 16;" :: "r"(dst), "l"(src) : "memory")
#define CP_COMMIT() asm volatile("cp.async.commit_group;" ::: "memory")

__device__ __forceinline__ uint32_t swz(uint32_t off) { return off ^ ((off >> 3) & 0x70); }

__device__ __forceinline__ void ldsm4(uint32_t* r, uint32_t addr) {
    asm volatile("ldmatrix.sync.aligned.m8n8.x4.shared.b16 {%0,%1,%2,%3}, [%4];"
        : "=r"(r[0]), "=r"(r[1]), "=r"(r[2]), "=r"(r[3]) : "r"(addr));
}
__device__ __forceinline__ void mma_bf16(float* c, const uint32_t* a, uint32_t b0, uint32_t b1) {
    asm volatile("mma.sync.aligned.m16n8k16.row.col.f32.bf16.bf16.f32 "
        "{%0,%1,%2,%3}, {%4,%5,%6,%7}, {%8,%9}, {%0,%1,%2,%3};"
        : "+f"(c[0]), "+f"(c[1]), "+f"(c[2]), "+f"(c[3])
        : "r"(a[0]), "r"(a[1]), "r"(a[2]), "r"(a[3]), "r"(b0), "r"(b1));
}
__device__ __forceinline__ bool lex_less(float v1, int i1, float v2, int i2) {
    return v1 < v2 || (v1 == v2 && i1 < i2);
}

// ===========================================================================
// small kernels
// ===========================================================================
__global__ void init_kernel() {
    int t = blockIdx.x * blockDim.x + threadIdx.x;
    if (t < KC) g_counts[t] = 0;
}

__global__ void cvt_kernel(const float* __restrict__ src, __nv_bfloat16* __restrict__ dst, int n) {
    int stride = gridDim.x * blockDim.x;
    for (int i = blockIdx.x * blockDim.x + threadIdx.x; i < n; i += stride)
        dst[i] = __float2bfloat16(src[i]);
}

__global__ void norms_x_kernel(const float* __restrict__ x) {
    int warp = (blockIdx.x * blockDim.x + threadIdx.x) >> 5;
    int lane = threadIdx.x & 31;
    if (warp >= N_IN) return;
    const float* r = x + (size_t)warp * DIM;
    float s = 0.f;
    #pragma unroll
    for (int i = 0; i < DIM / 32; i++) {
        float v = r[lane + i * 32];
        s = __fadd_rn(s, __fmul_rn(v, v));
    }
    #pragma unroll
    for (int o = 16; o > 0; o >>= 1)
        s = __fadd_rn(s, __shfl_xor_sync(0xffffffffu, s, o));
    if (lane == 0) g_A[warp] = s;
}

__global__ void norms_w_kernel(const float* __restrict__ w) {
    int warp = (blockIdx.x * blockDim.x + threadIdx.x) >> 5;
    int lane = threadIdx.x & 31;
    if (warp >= KC) return;
    const float* r = w + (size_t)warp * DIM;
    float s = 0.f;
    #pragma unroll
    for (int i = 0; i < DIM / 32; i++) {
        float v = r[lane + i * 32];
        s = __fadd_rn(s, __fmul_rn(v, v));
    }
    #pragma unroll
    for (int o = 16; o > 0; o >>= 1)
        s = __fadd_rn(s, __shfl_xor_sync(0xffffffffu, s, o));
    if (lane == 0) g_B[warp] = s;
}

// zero encodings; region byte offset is 8 mod 16 -> scalar head/tail + float4 body
__global__ void zero_enc_kernel(float* __restrict__ enc) {
    const long long n4 = ((long long)N_IN * KC - 4) / 4;
    float4* v4 = (float4*)(enc + 2);
    long long stride = (long long)gridDim.x * blockDim.x;
    long long i0 = blockIdx.x * (long long)blockDim.x + threadIdx.x;
    float4 z = make_float4(0.f, 0.f, 0.f, 0.f);
    for (long long i = i0; i < n4; i += stride) v4[i] = z;
    if (i0 == 0) {
        enc[0] = 0.f; enc[1] = 0.f;
        enc[(long long)N_IN * KC - 2] = 0.f;
        enc[(long long)N_IN * KC - 1] = 0.f;
    }
}

// ===========================================================================
// bf16 mma.sync distance GEMM + top-2 shortlist + in-kernel exact fp32 refine
// CTA: 128 threads (4 warps = 2m x 2n, warp tile 64x64), 128 rows x 4096 cols.
// STAGES=3 x 16KB x 2 = 96KB smem -> 2 CTAs/SM, 256 CTAs in one wave.
// Pipeline order (race-free with 3 stages): wait -> barrier -> issue c+2 -> mma c.
// ===========================================================================
__global__ __launch_bounds__(128, 2)
void gemm_mma_kernel(const float* __restrict__ x, const float* __restrict__ w) {
    extern __shared__ char smem[];
    const uint32_t sbase = smem_u32(smem);
    const int tid  = threadIdx.x;
    const int wid  = tid >> 5;
    const int lane = tid & 31;
    const int warp_m = wid & 1;       // 64-row slab
    const int warp_n = wid >> 1;      // 64-col slab
    const int row0 = blockIdx.x * M_TILE;

    const uint32_t A_OFF = 0;
    const uint32_t B_OFF = STAGES * STG_BYTES;   // 48KB

    // ldmatrix per-lane geometry (canonical x4 non-trans)
    const int a_row_l = (((lane >> 3) & 1) << 3) + (lane & 7);
    const int a_seg   = (lane >> 4) << 4;
    const int b_n_l   = ((lane >> 4) << 3) + (lane & 7);
    const int b_seg   = ((lane >> 3) & 1) << 4;

    float acc[4][8][4];
    #pragma unroll
    for (int mi = 0; mi < 4; mi++)
        #pragma unroll
        for (int ni = 0; ni < 8; ni++)
            #pragma unroll
            for (int q = 0; q < 4; q++) acc[mi][ni][q] = 0.f;

    // top-2 per local row (8 local rows per thread), lex-sorted ascending
    float cv[8][2];
    int   ci[8][2];
    float Arow[8];
    #pragma unroll
    for (int lr = 0; lr < 8; lr++) {
        cv[lr][0] = cv[lr][1] = 3.4e38f;
        ci[lr][0] = ci[lr][1] = 0x7fffffff;
        int mi = lr >> 1, h = lr & 1;
        Arow[lr] = g_A[row0 + warp_m * 64 + mi * 16 + h * 8 + (lane >> 2)];
    }

    const __nv_bfloat16* xs = g_Xbf + (size_t)row0 * DIM;

    // chunk issue lambda-equivalent
    #define ISSUE_CHUNK(cc_) do {                                             \
        const int s_  = (cc_) % 3;                                            \
        const int nt_ = (cc_) >> 2;                                           \
        const int kc_ = (cc_) & 3;                                            \
        const uint32_t Ab_ = sbase + A_OFF + s_ * STG_BYTES;                  \
        const __nv_bfloat16* ga_ = xs + kc_ * K_CH;                           \
        _Pragma("unroll")                                                     \
        for (int i = 0; i < 8; i++) {                                         \
            int id = tid + i * 128;                                           \
            int r = id >> 3, k8 = id & 7;                                     \
            CP_ASYNC16(Ab_ + swz(r * 128 + k8 * 16), ga_ + (size_t)r * DIM + k8 * 8); \
        }                                                                     \
        const uint32_t Bb_ = sbase + B_OFF + s_ * STG_BYTES;                  \
        const __nv_bfloat16* gb_ = g_Wbf + (size_t)(nt_ * NT_COLS) * DIM + kc_ * K_CH; \
        _Pragma("unroll")                                                     \
        for (int i = 0; i < 8; i++) {                                         \
            int id = tid + i * 128;                                           \
            int r = id >> 3, k8 = id & 7;                                     \
            CP_ASYNC16(Bb_ + swz(r * 128 + k8 * 16), gb_ + (size_t)r * DIM + k8 * 8); \
        }                                                                     \
        CP_COMMIT();                                                          \
    } while (0)

    // prologue: 2 chunks in flight
    ISSUE_CHUNK(0);
    ISSUE_CHUNK(1);

    #pragma unroll 1
    for (int c = 0; c < N_CHUNKS; c++) {
        if (c + 1 < N_CHUNKS) asm volatile("cp.async.wait_group 1;" ::: "memory");
        else                  asm volatile("cp.async.wait_group 0;" ::: "memory");
        __syncthreads();
        if (c + 2 < N_CHUNKS) ISSUE_CHUNK(c + 2);

        const int sm_ = c % 3;
        const uint32_t Ab = sbase + A_OFF + sm_ * STG_BYTES;
        const uint32_t Bb = sbase + B_OFF + sm_ * STG_BYTES;

        #pragma unroll
        for (int k16 = 0; k16 < 4; k16++) {
            const int kb = k16 * 32;
            uint32_t af[4][4];
            #pragma unroll
            for (int mi = 0; mi < 4; mi++)
                ldsm4(af[mi], Ab + swz((warp_m * 64 + mi * 16 + a_row_l) * 128
                                       + kb + a_seg));
            uint32_t bf[4][4];
            #pragma unroll
            for (int p = 0; p < 4; p++)
                ldsm4(bf[p], Bb + swz((warp_n * 64 + p * 16 + b_n_l) * 128
                                      + kb + b_seg));
            #pragma unroll
            for (int mi = 0; mi < 4; mi++)
                #pragma unroll
                for (int ni = 0; ni < 8; ni++)
                    mma_bf16(acc[mi][ni], af[mi],
                             bf[ni >> 1][(ni & 1) * 2], bf[ni >> 1][(ni & 1) * 2 + 1]);
        }

        if ((c & 3) == 3) {
            // N-tile finished: approx distances, maintain top-2 shortlist
            const int nt = c >> 2;
            const int colbase = nt * NT_COLS + warp_n * 64;
            #pragma unroll
            for (int mi = 0; mi < 4; mi++)
                #pragma unroll
                for (int h = 0; h < 2; h++) {
                    const int lr = mi * 2 + h;
                    #pragma unroll
                    for (int ni = 0; ni < 8; ni++)
                        #pragma unroll
                        for (int cc = 0; cc < 2; cc++) {
                            const int col = colbase + ni * 8 + 2 * (lane & 3) + cc;
                            float d = acc[mi][ni][h * 2 + cc];
                            float u = __fadd_rn(Arow[lr], g_B[col]);
                            float v = __fsub_rn(u, __fmul_rn(2.0f, d));
                            if (lex_less(v, col, cv[lr][1], ci[lr][1])) {
                                if (lex_less(v, col, cv[lr][0], ci[lr][0])) {
                                    cv[lr][1] = cv[lr][0]; ci[lr][1] = ci[lr][0];
                                    cv[lr][0] = v;         ci[lr][0] = col;
                                } else {
                                    cv[lr][1] = v;         ci[lr][1] = col;
                                }
                            }
                            acc[mi][ni][h * 2 + cc] = 0.f;
                        }
                }
        }
    }

    // gather shortlist to smem: 128 rows x 16 entries
    __syncthreads();
    float* redv = (float*)smem;                    // 8KB
    int*   redi = (int*)(smem + 128 * 16 * 4);     // 8KB
    #pragma unroll
    for (int lr = 0; lr < 8; lr++) {
        int mi = lr >> 1, h = lr & 1;
        const int row = warp_m * 64 + mi * 16 + h * 8 + (lane >> 2);
        const int slot = (warp_n * 4 + (lane & 3)) * 2;
        #pragma unroll
        for (int j = 0; j < 2; j++) {
            redv[row * 16 + slot + j] = cv[lr][j];
            redi[row * 16 + slot + j] = ci[lr][j];
        }
    }
    __syncthreads();

    // exact fp32 refine: one thread per row
    {
        const int row = row0 + tid;
        float gmin = 3.4e38f;
        #pragma unroll
        for (int j = 0; j < 16; j++)
            gmin = fminf(gmin, redv[tid * 16 + j]);
        const float thresh = gmin + EPS;
        const float Ar = g_A[row];
        const float* xr = x + (size_t)row * DIM;

        float bestv = 3.4e38f;
        int   besti = 0x7fffffff;
        for (int j = 0; j < 16; j++) {
            float va = redv[tid * 16 + j];
            int   col = redi[tid * 16 + j];
            if (va > thresh || col == 0x7fffffff) continue;
            const float* wr = w + (size_t)col * DIM;
            float dot = 0.f;
            #pragma unroll 8
            for (int k = 0; k < DIM; k++)
                dot = fmaf(xr[k], __ldg(wr + k), dot);
            float u = __fadd_rn(Ar, g_B[col]);
            float ve = __fsub_rn(u, __fmul_rn(2.0f, dot));
            if (lex_less(ve, col, bestv, besti)) { bestv = ve; besti = col; }
        }
        g_argmin[row] = besti;
    }
}

// ===========================================================================
// epilogue + finalize
// ===========================================================================
__global__ __launch_bounds__(256)
void epilogue_kernel(const float* __restrict__ x, const float* __restrict__ w,
                     float* __restrict__ out_qst, float* __restrict__ out_enc) {
    __shared__ double sred[256];
    const int tid = threadIdx.x;
    const int rowLocal = tid >> 2;
    const int sub = tid & 3;
    const int row = blockIdx.x * 64 + rowLocal;
    const int idx = g_argmin[row];

    const float* wr = w + (size_t)idx * DIM;
    const float* xr = x + (size_t)row * DIM;
    float* qr = out_qst + (size_t)row * DIM;

    double ls = 0.0;
    #pragma unroll 8
    for (int u = 0; u < DIM / 4; u++) {
        int e = u * 4 + sub;
        float wv = wr[e];
        float xv = xr[e];
        float dlt = __fsub_rn(wv, xv);
        qr[e] = __fadd_rn(xv, dlt);
        float t = __fmul_rn(dlt, dlt);
        ls += (double)t;
    }
    if (sub == 0) {
        out_enc[(size_t)row * KC + idx] = 1.0f;
        atomicAdd(&g_counts[idx], 1);
    }
    sred[tid] = ls;
    __syncthreads();
    #pragma unroll
    for (int s = 128; s > 0; s >>= 1) {
        if (tid < s) sred[tid] += sred[tid + s];
        __syncthreads();
    }
    if (tid == 0) g_partial[blockIdx.x] = sred[0];
}

__global__ __launch_bounds__(256)
void finalize_kernel(float* __restrict__ out_loss, float* __restrict__ out_perp) {
    __shared__ double sred[256];
    const int tid = threadIdx.x;

    double s = g_partial[tid] + g_partial[tid + 256];
    sred[tid] = s;
    __syncthreads();
    #pragma unroll
    for (int st = 128; st > 0; st >>= 1) {
        if (tid < st) sred[tid] += sred[tid + st];
        __syncthreads();
    }
    if (tid == 0) {
        double total = sred[0];
        float m = (float)(total / (double)((long long)N_IN * DIM));
        *out_loss = __fadd_rn(m, __fmul_rn(0.25f, m));
    }
    __syncthreads();

    double ps = 0.0;
    #pragma unroll
    for (int i = 0; i < KC / 256; i++) {
        int k = tid + i * 256;
        float p = (float)g_counts[k] * (1.0f / (float)N_IN);
        float term = p * logf(__fadd_rn(p, 1e-10f));
        ps += (double)term;
    }
    sred[tid] = ps;
    __syncthreads();
    #pragma unroll
    for (int st = 128; st > 0; st >>= 1) {
        if (tid < st) sred[tid] += sred[tid + st];
        __syncthreads();
    }
    if (tid == 0) *out_perp = expf((float)(-sred[0]));
}

// ===========================================================================
extern "C" void kernel_launch(void* const* d_in, const int* in_sizes, int n_in,
                              void* d_out, int out_size) {
    const float* x = (const float*)d_in[0];
    const float* w = (const float*)d_in[1];
    if (n_in >= 2 && in_sizes[0] == KC * DIM && in_sizes[1] == N_IN * DIM) {
        x = (const float*)d_in[1];
        w = (const float*)d_in[0];
    }

    float* out = (float*)d_out;
    float* out_loss = out;
    float* out_qst  = out + 1;
    float* out_perp = out + 1 + (size_t)N_IN * DIM;
    float* out_enc  = out + 2 + (size_t)N_IN * DIM;

    __nv_bfloat16* xbf = nullptr; __nv_bfloat16* wbf = nullptr;
    cudaGetSymbolAddress((void**)&xbf, g_Xbf);
    cudaGetSymbolAddress((void**)&wbf, g_Wbf);

    const int SMEM_BYTES = 2 * STAGES * STG_BYTES;   // 96KB
    cudaFuncSetAttribute(gemm_mma_kernel, cudaFuncAttributeMaxDynamicSharedMemorySize, SMEM_BYTES);

    init_kernel<<<(KC + 255) / 256, 256>>>();
    cvt_kernel<<<2048, 256>>>(x, xbf, N_IN * DIM);
    cvt_kernel<<<512, 256>>>(w, wbf, KC * DIM);
    norms_x_kernel<<<N_IN / 8, 256>>>(x);
    norms_w_kernel<<<KC / 8, 256>>>(w);
    zero_enc_kernel<<<8192, 256>>>(out_enc);

    gemm_mma_kernel<<<N_IN / M_TILE, 128, SMEM_BYTES>>>(x, w);

    epilogue_kernel<<<N_IN / 64, 256>>>(x, w, out_qst, out_enc);
    finalize_kernel<<<1, 256>>>(out_loss, out_perp);
}

// round 7
// speedup vs baseline: 4.1693x; 1.0625x over previous
#include <cuda_runtime.h>
#include <cuda_bf16.h>
#include <math.h>
#include <stdint.h>

#define N_IN  32768
#define KC    4096
#define DIM   256
#define M_TILE 128
#define NT_COLS 128
#define K_CH   64                        // bf16 elems per chunk = 128B per row
#define N_NT   (KC / NT_COLS)            // 32
#define CH_PER_NT (DIM / K_CH)           // 4
#define N_CHUNKS (N_NT * CH_PER_NT)      // 128 B-chunks
#define STAGES 3
#define STG_BYTES (M_TILE * 128)         // 16KB per B stage
#define A_BYTES  (M_TILE * DIM * 2)      // 64KB resident A
#define EPS 5e-4f

// ---- scratch (device globals; no allocation allowed) ----
__device__ __nv_bfloat16 g_Xbf[(size_t)N_IN * DIM];   // 16MB
__device__ __nv_bfloat16 g_Wbf[(size_t)KC   * DIM];   // 2MB
__device__ float  g_A[N_IN];
__device__ float  g_B[KC];
__device__ int    g_argmin[N_IN];
__device__ int    g_counts[KC];
__device__ double g_partial[512];

// ===========================================================================
// helpers
// ===========================================================================
__device__ __forceinline__ uint32_t smem_u32(const void* p) {
    uint32_t a;
    asm("{ .reg .u64 t; cvta.to.shared.u64 t, %1; cvt.u32.u64 %0, t; }" : "=r"(a) : "l"(p));
    return a;
}
#define CP_ASYNC16(dst, src) \
    asm volatile("cp.async.cg.shared.global [%0], [%1], 16;" :: "r"(dst), "l"(src) : "memory")
#define CP_COMMIT() asm volatile("cp.async.commit_group;" ::: "memory")

__device__ __forceinline__ uint32_t swz(uint32_t off) { return off ^ ((off >> 3) & 0x70); }

__device__ __forceinline__ void ldsm4(uint32_t* r, uint32_t addr) {
    asm volatile("ldmatrix.sync.aligned.m8n8.x4.shared.b16 {%0,%1,%2,%3}, [%4];"
        : "=r"(r[0]), "=r"(r[1]), "=r"(r[2]), "=r"(r[3]) : "r"(addr));
}
__device__ __forceinline__ void mma_bf16(float* c, const uint32_t* a, uint32_t b0, uint32_t b1) {
    asm volatile("mma.sync.aligned.m16n8k16.row.col.f32.bf16.bf16.f32 "
        "{%0,%1,%2,%3}, {%4,%5,%6,%7}, {%8,%9}, {%0,%1,%2,%3};"
        : "+f"(c[0]), "+f"(c[1]), "+f"(c[2]), "+f"(c[3])
        : "r"(a[0]), "r"(a[1]), "r"(a[2]), "r"(a[3]), "r"(b0), "r"(b1));
}
__device__ __forceinline__ bool lex_less(float v1, int i1, float v2, int i2) {
    return v1 < v2 || (v1 == v2 && i1 < i2);
}

// ===========================================================================
// small kernels
// ===========================================================================
__global__ void init_kernel() {
    int t = blockIdx.x * blockDim.x + threadIdx.x;
    if (t < KC) g_counts[t] = 0;
}

// fused bf16 convert + row norms (exact same reduction order as before)
__global__ void prep_kernel(const float* __restrict__ src, __nv_bfloat16* __restrict__ dst,
                            float* __restrict__ norms, int nrows) {
    int warp = (blockIdx.x * blockDim.x + threadIdx.x) >> 5;
    int lane = threadIdx.x & 31;
    if (warp >= nrows) return;
    const float* r = src + (size_t)warp * DIM;
    __nv_bfloat16* d = dst + (size_t)warp * DIM;
    float s = 0.f;
    #pragma unroll
    for (int i = 0; i < DIM / 32; i++) {
        float v = r[lane + i * 32];
        d[lane + i * 32] = __float2bfloat16(v);
        s = __fadd_rn(s, __fmul_rn(v, v));
    }
    #pragma unroll
    for (int o = 16; o > 0; o >>= 1)
        s = __fadd_rn(s, __shfl_xor_sync(0xffffffffu, s, o));
    if (lane == 0) norms[warp] = s;
}

// ===========================================================================
// bf16 mma.sync distance GEMM + top-2 shortlist + exact fp32 refine
// + fused zeroing of this CTA's 128 encoding rows (2MB) under the compute.
// A tile (64KB) resident in smem; only B streamed (3 stages, depth-2).
// ===========================================================================
__global__ __launch_bounds__(128, 2)
void gemm_mma_kernel(const float* __restrict__ x, const float* __restrict__ w,
                     float* __restrict__ out_enc) {
    extern __shared__ char smem[];
    const uint32_t sbase = smem_u32(smem);
    const int tid  = threadIdx.x;
    const int wid  = tid >> 5;
    const int lane = tid & 31;
    const int warp_m = wid & 1;       // 64-row slab
    const int warp_n = wid >> 1;      // 64-col slab
    const int row0 = blockIdx.x * M_TILE;

    const uint32_t A_OFF = 0;                    // 64KB: 4 blocks of 16KB (k-chunk major)
    const uint32_t B_OFF = A_BYTES;              // 48KB B stages

    // enc slice for this CTA: rows [row0, row0+128)
    float* enc_slice = out_enc + (size_t)row0 * KC;
    float4* encz = (float4*)(enc_slice + 2);     // 16B-aligned (base is 8-mod-16)
    const int N_F4 = (M_TILE * KC - 4) / 4;      // 131071

    // ldmatrix per-lane geometry (canonical x4 non-trans)
    const int a_row_l = (((lane >> 3) & 1) << 3) + (lane & 7);
    const int a_seg   = (lane >> 4) << 4;
    const int b_n_l   = ((lane >> 4) << 3) + (lane & 7);
    const int b_seg   = ((lane >> 3) & 1) << 4;

    float acc[4][8][4];
    #pragma unroll
    for (int mi = 0; mi < 4; mi++)
        #pragma unroll
        for (int ni = 0; ni < 8; ni++)
            #pragma unroll
            for (int q = 0; q < 4; q++) acc[mi][ni][q] = 0.f;

    // top-2 per local row (8 local rows per thread), lex-sorted ascending
    float cv[8][2];
    int   ci[8][2];
    float Arow[8];
    #pragma unroll
    for (int lr = 0; lr < 8; lr++) {
        cv[lr][0] = cv[lr][1] = 3.4e38f;
        ci[lr][0] = ci[lr][1] = 0x7fffffff;
        int mi = lr >> 1, h = lr & 1;
        Arow[lr] = g_A[row0 + warp_m * 64 + mi * 16 + h * 8 + (lane >> 2)];
    }

    const __nv_bfloat16* xs = g_Xbf + (size_t)row0 * DIM;

    // ---- load resident A (4 blocks x 16KB), one commit group ----
    #pragma unroll
    for (int blk = 0; blk < 4; blk++) {
        const uint32_t Ab = sbase + A_OFF + blk * 16384;
        const __nv_bfloat16* ga = xs + blk * K_CH;
        #pragma unroll
        for (int i = 0; i < 8; i++) {
            int id = tid + i * 128;
            int r = id >> 3, k8 = id & 7;
            CP_ASYNC16(Ab + swz(r * 128 + k8 * 16), ga + (size_t)r * DIM + k8 * 8);
        }
    }
    CP_COMMIT();

    // ---- B chunk issue ----
    #define ISSUE_B(cc_) do {                                                 \
        const int s_  = (cc_) % 3;                                            \
        const int nt_ = (cc_) >> 2;                                           \
        const int kc_ = (cc_) & 3;                                            \
        const uint32_t Bb_ = sbase + B_OFF + s_ * STG_BYTES;                  \
        const __nv_bfloat16* gb_ = g_Wbf + (size_t)(nt_ * NT_COLS) * DIM + kc_ * K_CH; \
        _Pragma("unroll")                                                     \
        for (int i = 0; i < 8; i++) {                                         \
            int id = tid + i * 128;                                           \
            int r = id >> 3, k8 = id & 7;                                     \
            CP_ASYNC16(Bb_ + swz(r * 128 + k8 * 16), gb_ + (size_t)r * DIM + k8 * 8); \
        }                                                                     \
        CP_COMMIT();                                                          \
    } while (0)

    ISSUE_B(0);
    ISSUE_B(1);

    #pragma unroll 1
    for (int c = 0; c < N_CHUNKS; c++) {
        if (c + 1 < N_CHUNKS) asm volatile("cp.async.wait_group 1;" ::: "memory");
        else                  asm volatile("cp.async.wait_group 0;" ::: "memory");
        __syncthreads();
        if (c + 2 < N_CHUNKS) ISSUE_B(c + 2);

        // fused enc zeroing: 8 coalesced float4 stores per thread per chunk
        {
            const float4 z4 = make_float4(0.f, 0.f, 0.f, 0.f);
            const int base = c * 1024 + tid;
            #pragma unroll
            for (int j = 0; j < 8; j++) {
                int idx = base + j * 128;
                if (idx < N_F4) encz[idx] = z4;
            }
            if (c == 0 && tid == 0) {
                enc_slice[0] = 0.f; enc_slice[1] = 0.f;
                enc_slice[(size_t)M_TILE * KC - 2] = 0.f;
                enc_slice[(size_t)M_TILE * KC - 1] = 0.f;
            }
        }

        const uint32_t Ab = sbase + A_OFF + (c & 3) * 16384;
        const uint32_t Bb = sbase + B_OFF + (c % 3) * STG_BYTES;

        #pragma unroll
        for (int k16 = 0; k16 < 4; k16++) {
            const int kb = k16 * 32;
            uint32_t af[4][4];
            #pragma unroll
            for (int mi = 0; mi < 4; mi++)
                ldsm4(af[mi], Ab + swz((warp_m * 64 + mi * 16 + a_row_l) * 128
                                       + kb + a_seg));
            uint32_t bf[4][4];
            #pragma unroll
            for (int p = 0; p < 4; p++)
                ldsm4(bf[p], Bb + swz((warp_n * 64 + p * 16 + b_n_l) * 128
                                      + kb + b_seg));
            #pragma unroll
            for (int mi = 0; mi < 4; mi++)
                #pragma unroll
                for (int ni = 0; ni < 8; ni++)
                    mma_bf16(acc[mi][ni], af[mi],
                             bf[ni >> 1][(ni & 1) * 2], bf[ni >> 1][(ni & 1) * 2 + 1]);
        }

        if ((c & 3) == 3) {
            // N-tile finished: approx distances, maintain top-2 shortlist
            const int nt = c >> 2;
            const int colbase = nt * NT_COLS + warp_n * 64;
            #pragma unroll
            for (int mi = 0; mi < 4; mi++)
                #pragma unroll
                for (int h = 0; h < 2; h++) {
                    const int lr = mi * 2 + h;
                    #pragma unroll
                    for (int ni = 0; ni < 8; ni++)
                        #pragma unroll
                        for (int cc = 0; cc < 2; cc++) {
                            const int col = colbase + ni * 8 + 2 * (lane & 3) + cc;
                            float d = acc[mi][ni][h * 2 + cc];
                            float u = __fadd_rn(Arow[lr], g_B[col]);
                            float v = __fsub_rn(u, __fmul_rn(2.0f, d));
                            if (lex_less(v, col, cv[lr][1], ci[lr][1])) {
                                if (lex_less(v, col, cv[lr][0], ci[lr][0])) {
                                    cv[lr][1] = cv[lr][0]; ci[lr][1] = ci[lr][0];
                                    cv[lr][0] = v;         ci[lr][0] = col;
                                } else {
                                    cv[lr][1] = v;         ci[lr][1] = col;
                                }
                            }
                            acc[mi][ni][h * 2 + cc] = 0.f;
                        }
                }
        }
    }

    // gather shortlist to smem (reuse A region): 128 rows x 16 entries
    __syncthreads();
    float* redv = (float*)smem;                    // 8KB
    int*   redi = (int*)(smem + 128 * 16 * 4);     // 8KB
    #pragma unroll
    for (int lr = 0; lr < 8; lr++) {
        int mi = lr >> 1, h = lr & 1;
        const int row = warp_m * 64 + mi * 16 + h * 8 + (lane >> 2);
        const int slot = (warp_n * 4 + (lane & 3)) * 2;
        #pragma unroll
        for (int j = 0; j < 2; j++) {
            redv[row * 16 + slot + j] = cv[lr][j];
            redi[row * 16 + slot + j] = ci[lr][j];
        }
    }
    __syncthreads();

    // exact fp32 refine: one thread per row
    {
        const int row = row0 + tid;
        float gmin = 3.4e38f;
        #pragma unroll
        for (int j = 0; j < 16; j++)
            gmin = fminf(gmin, redv[tid * 16 + j]);
        const float thresh = gmin + EPS;
        const float Ar = g_A[row];
        const float* xr = x + (size_t)row * DIM;

        float bestv = 3.4e38f;
        int   besti = 0x7fffffff;
        for (int j = 0; j < 16; j++) {
            float va = redv[tid * 16 + j];
            int   col = redi[tid * 16 + j];
            if (va > thresh || col == 0x7fffffff) continue;
            const float* wr = w + (size_t)col * DIM;
            float dot = 0.f;
            #pragma unroll 8
            for (int k = 0; k < DIM; k++)
                dot = fmaf(xr[k], __ldg(wr + k), dot);
            float u = __fadd_rn(Ar, g_B[col]);
            float ve = __fsub_rn(u, __fmul_rn(2.0f, dot));
            if (lex_less(ve, col, bestv, besti)) { bestv = ve; besti = col; }
        }
        g_argmin[row] = besti;
    }
}

// ===========================================================================
// epilogue + finalize
// ===========================================================================
__global__ __launch_bounds__(256)
void epilogue_kernel(const float* __restrict__ x, const float* __restrict__ w,
                     float* __restrict__ out_qst, float* __restrict__ out_enc) {
    __shared__ double sred[256];
    const int tid = threadIdx.x;
    const int rowLocal = tid >> 2;
    const int sub = tid & 3;
    const int row = blockIdx.x * 64 + rowLocal;
    const int idx = g_argmin[row];

    const float* wr = w + (size_t)idx * DIM;
    const float* xr = x + (size_t)row * DIM;
    float* qr = out_qst + (size_t)row * DIM;

    double ls = 0.0;
    #pragma unroll 8
    for (int u = 0; u < DIM / 4; u++) {
        int e = u * 4 + sub;
        float wv = wr[e];
        float xv = xr[e];
        float dlt = __fsub_rn(wv, xv);
        qr[e] = __fadd_rn(xv, dlt);
        float t = __fmul_rn(dlt, dlt);
        ls += (double)t;
    }
    if (sub == 0) {
        out_enc[(size_t)row * KC + idx] = 1.0f;
        atomicAdd(&g_counts[idx], 1);
    }
    sred[tid] = ls;
    __syncthreads();
    #pragma unroll
    for (int s = 128; s > 0; s >>= 1) {
        if (tid < s) sred[tid] += sred[tid + s];
        __syncthreads();
    }
    if (tid == 0) g_partial[blockIdx.x] = sred[0];
}

__global__ __launch_bounds__(256)
void finalize_kernel(float* __restrict__ out_loss, float* __restrict__ out_perp) {
    __shared__ double sred[256];
    const int tid = threadIdx.x;

    double s = g_partial[tid] + g_partial[tid + 256];
    sred[tid] = s;
    __syncthreads();
    #pragma unroll
    for (int st = 128; st > 0; st >>= 1) {
        if (tid < st) sred[tid] += sred[tid + st];
        __syncthreads();
    }
    if (tid == 0) {
        double total = sred[0];
        float m = (float)(total / (double)((long long)N_IN * DIM));
        *out_loss = __fadd_rn(m, __fmul_rn(0.25f, m));
    }
    __syncthreads();

    double ps = 0.0;
    #pragma unroll
    for (int i = 0; i < KC / 256; i++) {
        int k = tid + i * 256;
        float p = (float)g_counts[k] * (1.0f / (float)N_IN);
        float term = p * logf(__fadd_rn(p, 1e-10f));
        ps += (double)term;
    }
    sred[tid] = ps;
    __syncthreads();
    #pragma unroll
    for (int st = 128; st > 0; st >>= 1) {
        if (tid < st) sred[tid] += sred[tid + st];
        __syncthreads();
    }
    if (tid == 0) *out_perp = expf((float)(-sred[0]));
}

// ===========================================================================
extern "C" void kernel_launch(void* const* d_in, const int* in_sizes, int n_in,
                              void* d_out, int out_size) {
    const float* x = (const float*)d_in[0];
    const float* w = (const float*)d_in[1];
    if (n_in >= 2 && in_sizes[0] == KC * DIM && in_sizes[1] == N_IN * DIM) {
        x = (const float*)d_in[1];
        w = (const float*)d_in[0];
    }

    float* out = (float*)d_out;
    float* out_loss = out;
    float* out_qst  = out + 1;
    float* out_perp = out + 1 + (size_t)N_IN * DIM;
    float* out_enc  = out + 2 + (size_t)N_IN * DIM;

    __nv_bfloat16* xbf = nullptr; __nv_bfloat16* wbf = nullptr;
    float* ga = nullptr; float* gb = nullptr;
    cudaGetSymbolAddress((void**)&xbf, g_Xbf);
    cudaGetSymbolAddress((void**)&wbf, g_Wbf);
    cudaGetSymbolAddress((void**)&ga, g_A);
    cudaGetSymbolAddress((void**)&gb, g_B);

    const int SMEM_BYTES = A_BYTES + STAGES * STG_BYTES;   // 112KB
    cudaFuncSetAttribute(gemm_mma_kernel, cudaFuncAttributeMaxDynamicSharedMemorySize, SMEM_BYTES);

    init_kernel<<<(KC + 255) / 256, 256>>>();
    prep_kernel<<<N_IN / 8, 256>>>(x, xbf, ga, N_IN);
    prep_kernel<<<KC / 8, 256>>>(w, wbf, gb, KC);

    gemm_mma_kernel<<<N_IN / M_TILE, 128, SMEM_BYTES>>>(x, w, out_enc);

    epilogue_kernel<<<N_IN / 64, 256>>>(x, w, out_qst, out_enc);
    finalize_kernel<<<1, 256>>>(out_loss, out_perp);
}

// round 8
// speedup vs baseline: 5.2533x; 1.2600x over previous
#include <cuda_runtime.h>
#include <cuda_bf16.h>
#include <math.h>
#include <stdint.h>

#define N_IN  32768
#define KC    4096
#define DIM   256
#define M_TILE 64
#define NT_COLS 64
#define K_CH   64                        // bf16 elems per chunk = 128B per row
#define N_NT   (KC / NT_COLS)            // 64
#define CH_PER_NT (DIM / K_CH)           // 4
#define N_CHUNKS (N_NT * CH_PER_NT)      // 256 B-chunks
#define STAGES 3
#define STG_BYTES (NT_COLS * 128)        // 8KB per B stage
#define A_BYTES  (M_TILE * DIM * 2)      // 32KB resident A
#define EPS 5e-4f

// ---- scratch (device globals; no allocation allowed) ----
__device__ __nv_bfloat16 g_Xbf[(size_t)N_IN * DIM];   // 16MB
__device__ __nv_bfloat16 g_Wbf[(size_t)KC   * DIM];   // 2MB
__device__ float  g_A[N_IN];
__device__ float  g_B[KC];
__device__ int    g_argmin[N_IN];
__device__ int    g_counts[KC];
__device__ double g_partial[512];

// ===========================================================================
// helpers
// ===========================================================================
__device__ __forceinline__ uint32_t smem_u32(const void* p) {
    uint32_t a;
    asm("{ .reg .u64 t; cvta.to.shared.u64 t, %1; cvt.u32.u64 %0, t; }" : "=r"(a) : "l"(p));
    return a;
}
#define CP_ASYNC16(dst, src) \
    asm volatile("cp.async.cg.shared.global [%0], [%1], 16;" :: "r"(dst), "l"(src) : "memory")
#define CP_COMMIT() asm volatile("cp.async.commit_group;" ::: "memory")

__device__ __forceinline__ uint32_t swz(uint32_t off) { return off ^ ((off >> 3) & 0x70); }

__device__ __forceinline__ void ldsm4(uint32_t* r, uint32_t addr) {
    asm volatile("ldmatrix.sync.aligned.m8n8.x4.shared.b16 {%0,%1,%2,%3}, [%4];"
        : "=r"(r[0]), "=r"(r[1]), "=r"(r[2]), "=r"(r[3]) : "r"(addr));
}
__device__ __forceinline__ void mma_bf16(float* c, const uint32_t* a, uint32_t b0, uint32_t b1) {
    asm volatile("mma.sync.aligned.m16n8k16.row.col.f32.bf16.bf16.f32 "
        "{%0,%1,%2,%3}, {%4,%5,%6,%7}, {%8,%9}, {%0,%1,%2,%3};"
        : "+f"(c[0]), "+f"(c[1]), "+f"(c[2]), "+f"(c[3])
        : "r"(a[0]), "r"(a[1]), "r"(a[2]), "r"(a[3]), "r"(b0), "r"(b1));
}
__device__ __forceinline__ bool lex_less(float v1, int i1, float v2, int i2) {
    return v1 < v2 || (v1 == v2 && i1 < i2);
}

// ===========================================================================
// small kernels
// ===========================================================================
__global__ void init_kernel() {
    int t = blockIdx.x * blockDim.x + threadIdx.x;
    if (t < KC) g_counts[t] = 0;
}

// fused bf16 convert + row norms (exact same reduction order as before)
__global__ void prep_kernel(const float* __restrict__ src, __nv_bfloat16* __restrict__ dst,
                            float* __restrict__ norms, int nrows) {
    int warp = (blockIdx.x * blockDim.x + threadIdx.x) >> 5;
    int lane = threadIdx.x & 31;
    if (warp >= nrows) return;
    const float* r = src + (size_t)warp * DIM;
    __nv_bfloat16* d = dst + (size_t)warp * DIM;
    float s = 0.f;
    #pragma unroll
    for (int i = 0; i < DIM / 32; i++) {
        float v = r[lane + i * 32];
        d[lane + i * 32] = __float2bfloat16(v);
        s = __fadd_rn(s, __fmul_rn(v, v));
    }
    #pragma unroll
    for (int o = 16; o > 0; o >>= 1)
        s = __fadd_rn(s, __shfl_xor_sync(0xffffffffu, s, o));
    if (lane == 0) norms[warp] = s;
}

// ===========================================================================
// bf16 mma.sync distance GEMM + top-2 shortlist + exact fp32 refine
// CTA: 64 rows, 4 warps (2m x 2n), warp tile 32x32; A (32KB) resident;
// B streamed in 3 x 8KB stages (race-free: wait -> sync -> issue c+2 -> mma c).
// 56KB smem, <=128 regs -> 4 CTAs/SM = 16 warps. Fused enc zeroing.
// ===========================================================================
__global__ __launch_bounds__(128, 4)
void gemm_mma_kernel(const float* __restrict__ x, const float* __restrict__ w,
                     float* __restrict__ out_enc) {
    extern __shared__ char smem[];
    const uint32_t sbase = smem_u32(smem);
    const int tid  = threadIdx.x;
    const int wid  = tid >> 5;
    const int lane = tid & 31;
    const int warp_m = wid & 1;       // 32-row slab
    const int warp_n = wid >> 1;      // 32-col slab
    const int row0 = blockIdx.x * M_TILE;

    const uint32_t A_OFF = 0;                    // 32KB: 4 blocks of 8KB
    const uint32_t B_OFF = A_BYTES;              // 24KB B stages

    // enc slice for this CTA: rows [row0, row0+64)
    float* enc_slice = out_enc + (size_t)row0 * KC;
    float4* encz = (float4*)(enc_slice + 2);     // 16B-aligned (base is 8-mod-16)
    const int N_F4 = (M_TILE * KC - 4) / 4;      // 65535

    // ldmatrix per-lane geometry (canonical x4 non-trans)
    const int a_row_l = (((lane >> 3) & 1) << 3) + (lane & 7);
    const int a_seg   = (lane >> 4) << 4;
    const int b_n_l   = ((lane >> 4) << 3) + (lane & 7);
    const int b_seg   = ((lane >> 3) & 1) << 4;

    float acc[2][4][4];
    #pragma unroll
    for (int mi = 0; mi < 2; mi++)
        #pragma unroll
        for (int ni = 0; ni < 4; ni++)
            #pragma unroll
            for (int q = 0; q < 4; q++) acc[mi][ni][q] = 0.f;

    // top-2 per local row (4 local rows per thread), lex-sorted ascending
    float cv[4][2];
    int   ci[4][2];
    float Arow[4];
    #pragma unroll
    for (int lr = 0; lr < 4; lr++) {
        cv[lr][0] = cv[lr][1] = 3.4e38f;
        ci[lr][0] = ci[lr][1] = 0x7fffffff;
        int mi = lr >> 1, h = lr & 1;
        Arow[lr] = g_A[row0 + warp_m * 32 + mi * 16 + h * 8 + (lane >> 2)];
    }

    const __nv_bfloat16* xs = g_Xbf + (size_t)row0 * DIM;

    // ---- load resident A (4 blocks x 8KB), one commit group ----
    #pragma unroll
    for (int blk = 0; blk < 4; blk++) {
        const uint32_t Ab = sbase + A_OFF + blk * 8192;
        const __nv_bfloat16* ga = xs + blk * K_CH;
        #pragma unroll
        for (int i = 0; i < 4; i++) {
            int id = tid + i * 128;
            int r = id >> 3, k8 = id & 7;
            CP_ASYNC16(Ab + swz(r * 128 + k8 * 16), ga + (size_t)r * DIM + k8 * 8);
        }
    }
    CP_COMMIT();

    // ---- B chunk issue (64 rows x 128B = 512 x 16B; 4 per thread) ----
    #define ISSUE_B(cc_) do {                                                 \
        const int s_  = (cc_) % 3;                                            \
        const int nt_ = (cc_) >> 2;                                           \
        const int kc_ = (cc_) & 3;                                            \
        const uint32_t Bb_ = sbase + B_OFF + s_ * STG_BYTES;                  \
        const __nv_bfloat16* gb_ = g_Wbf + (size_t)(nt_ * NT_COLS) * DIM + kc_ * K_CH; \
        _Pragma("unroll")                                                     \
        for (int i = 0; i < 4; i++) {                                         \
            int id = tid + i * 128;                                           \
            int r = id >> 3, k8 = id & 7;                                     \
            CP_ASYNC16(Bb_ + swz(r * 128 + k8 * 16), gb_ + (size_t)r * DIM + k8 * 8); \
        }                                                                     \
        CP_COMMIT();                                                          \
    } while (0)

    ISSUE_B(0);
    ISSUE_B(1);

    #pragma unroll 1
    for (int c = 0; c < N_CHUNKS; c++) {
        if (c + 1 < N_CHUNKS) asm volatile("cp.async.wait_group 1;" ::: "memory");
        else                  asm volatile("cp.async.wait_group 0;" ::: "memory");
        __syncthreads();
        if (c + 2 < N_CHUNKS) ISSUE_B(c + 2);

        // fused enc zeroing: 2 coalesced float4 stores per thread per chunk
        {
            const float4 z4 = make_float4(0.f, 0.f, 0.f, 0.f);
            const int base = c * 256 + tid;
            if (base < N_F4)       encz[base] = z4;
            if (base + 128 < N_F4) encz[base + 128] = z4;
            if (c == 0 && tid == 0) {
                enc_slice[0] = 0.f; enc_slice[1] = 0.f;
                enc_slice[(size_t)M_TILE * KC - 2] = 0.f;
                enc_slice[(size_t)M_TILE * KC - 1] = 0.f;
            }
        }

        const uint32_t Ab = sbase + A_OFF + (c & 3) * 8192;
        const uint32_t Bb = sbase + B_OFF + (c % 3) * STG_BYTES;

        #pragma unroll
        for (int k16 = 0; k16 < 4; k16++) {
            const int kb = k16 * 32;
            uint32_t af[2][4];
            #pragma unroll
            for (int mi = 0; mi < 2; mi++)
                ldsm4(af[mi], Ab + swz((warp_m * 32 + mi * 16 + a_row_l) * 128
                                       + kb + a_seg));
            uint32_t bf[2][4];
            #pragma unroll
            for (int p = 0; p < 2; p++)
                ldsm4(bf[p], Bb + swz((warp_n * 32 + p * 16 + b_n_l) * 128
                                      + kb + b_seg));
            #pragma unroll
            for (int mi = 0; mi < 2; mi++)
                #pragma unroll
                for (int ni = 0; ni < 4; ni++)
                    mma_bf16(acc[mi][ni], af[mi],
                             bf[ni >> 1][(ni & 1) * 2], bf[ni >> 1][(ni & 1) * 2 + 1]);
        }

        if ((c & 3) == 3) {
            // N-tile finished: approx distances, maintain top-2 shortlist
            const int nt = c >> 2;
            const int colbase = nt * NT_COLS + warp_n * 32;
            #pragma unroll
            for (int mi = 0; mi < 2; mi++)
                #pragma unroll
                for (int h = 0; h < 2; h++) {
                    const int lr = mi * 2 + h;
                    #pragma unroll
                    for (int ni = 0; ni < 4; ni++)
                        #pragma unroll
                        for (int cc = 0; cc < 2; cc++) {
                            const int col = colbase + ni * 8 + 2 * (lane & 3) + cc;
                            float d = acc[mi][ni][h * 2 + cc];
                            float u = __fadd_rn(Arow[lr], g_B[col]);
                            float v = __fsub_rn(u, __fmul_rn(2.0f, d));
                            if (lex_less(v, col, cv[lr][1], ci[lr][1])) {
                                if (lex_less(v, col, cv[lr][0], ci[lr][0])) {
                                    cv[lr][1] = cv[lr][0]; ci[lr][1] = ci[lr][0];
                                    cv[lr][0] = v;         ci[lr][0] = col;
                                } else {
                                    cv[lr][1] = v;         ci[lr][1] = col;
                                }
                            }
                            acc[mi][ni][h * 2 + cc] = 0.f;
                        }
                }
        }
    }

    // gather shortlist to smem (reuse A region): 64 rows x 16 entries
    __syncthreads();
    float* redv = (float*)smem;                   // 4KB
    int*   redi = (int*)(smem + 64 * 16 * 4);     // 4KB
    #pragma unroll
    for (int lr = 0; lr < 4; lr++) {
        int mi = lr >> 1, h = lr & 1;
        const int row = warp_m * 32 + mi * 16 + h * 8 + (lane >> 2);
        const int slot = (warp_n * 4 + (lane & 3)) * 2;
        #pragma unroll
        for (int j = 0; j < 2; j++) {
            redv[row * 16 + slot + j] = cv[lr][j];
            redi[row * 16 + slot + j] = ci[lr][j];
        }
    }
    __syncthreads();

    // exact fp32 refine: one thread per row
    if (tid < M_TILE) {
        const int row = row0 + tid;
        float gmin = 3.4e38f;
        #pragma unroll
        for (int j = 0; j < 16; j++)
            gmin = fminf(gmin, redv[tid * 16 + j]);
        const float thresh = gmin + EPS;
        const float Ar = g_A[row];
        const float* xr = x + (size_t)row * DIM;

        float bestv = 3.4e38f;
        int   besti = 0x7fffffff;
        for (int j = 0; j < 16; j++) {
            float va = redv[tid * 16 + j];
            int   col = redi[tid * 16 + j];
            if (va > thresh || col == 0x7fffffff) continue;
            const float* wr = w + (size_t)col * DIM;
            float dot = 0.f;
            #pragma unroll 8
            for (int k = 0; k < DIM; k++)
                dot = fmaf(xr[k], __ldg(wr + k), dot);
            float u = __fadd_rn(Ar, g_B[col]);
            float ve = __fsub_rn(u, __fmul_rn(2.0f, dot));
            if (lex_less(ve, col, bestv, besti)) { bestv = ve; besti = col; }
        }
        g_argmin[row] = besti;
    }
}

// ===========================================================================
// epilogue + finalize
// ===========================================================================
__global__ __launch_bounds__(256)
void epilogue_kernel(const float* __restrict__ x, const float* __restrict__ w,
                     float* __restrict__ out_qst, float* __restrict__ out_enc) {
    __shared__ double sred[256];
    const int tid = threadIdx.x;
    const int rowLocal = tid >> 2;
    const int sub = tid & 3;
    const int row = blockIdx.x * 64 + rowLocal;
    const int idx = g_argmin[row];

    const float* wr = w + (size_t)idx * DIM;
    const float* xr = x + (size_t)row * DIM;
    float* qr = out_qst + (size_t)row * DIM;

    double ls = 0.0;
    #pragma unroll 8
    for (int u = 0; u < DIM / 4; u++) {
        int e = u * 4 + sub;
        float wv = wr[e];
        float xv = xr[e];
        float dlt = __fsub_rn(wv, xv);
        qr[e] = __fadd_rn(xv, dlt);
        float t = __fmul_rn(dlt, dlt);
        ls += (double)t;
    }
    if (sub == 0) {
        out_enc[(size_t)row * KC + idx] = 1.0f;
        atomicAdd(&g_counts[idx], 1);
    }
    sred[tid] = ls;
    __syncthreads();
    #pragma unroll
    for (int s = 128; s > 0; s >>= 1) {
        if (tid < s) sred[tid] += sred[tid + s];
        __syncthreads();
    }
    if (tid == 0) g_partial[blockIdx.x] = sred[0];
}

__global__ __launch_bounds__(256)
void finalize_kernel(float* __restrict__ out_loss, float* __restrict__ out_perp) {
    __shared__ double sred[256];
    const int tid = threadIdx.x;

    double s = g_partial[tid] + g_partial[tid + 256];
    sred[tid] = s;
    __syncthreads();
    #pragma unroll
    for (int st = 128; st > 0; st >>= 1) {
        if (tid < st) sred[tid] += sred[tid + st];
        __syncthreads();
    }
    if (tid == 0) {
        double total = sred[0];
        float m = (float)(total / (double)((long long)N_IN * DIM));
        *out_loss = __fadd_rn(m, __fmul_rn(0.25f, m));
    }
    __syncthreads();

    double ps = 0.0;
    #pragma unroll
    for (int i = 0; i < KC / 256; i++) {
        int k = tid + i * 256;
        float p = (float)g_counts[k] * (1.0f / (float)N_IN);
        float term = p * logf(__fadd_rn(p, 1e-10f));
        ps += (double)term;
    }
    sred[tid] = ps;
    __syncthreads();
    #pragma unroll
    for (int st = 128; st > 0; st >>= 1) {
        if (tid < st) sred[tid] += sred[tid + st];
        __syncthreads();
    }
    if (tid == 0) *out_perp = expf((float)(-sred[0]));
}

// ===========================================================================
extern "C" void kernel_launch(void* const* d_in, const int* in_sizes, int n_in,
                              void* d_out, int out_size) {
    const float* x = (const float*)d_in[0];
    const float* w = (const float*)d_in[1];
    if (n_in >= 2 && in_sizes[0] == KC * DIM && in_sizes[1] == N_IN * DIM) {
        x = (const float*)d_in[1];
        w = (const float*)d_in[0];
    }

    float* out = (float*)d_out;
    float* out_loss = out;
    float* out_qst  = out + 1;
    float* out_perp = out + 1 + (size_t)N_IN * DIM;
    float* out_enc  = out + 2 + (size_t)N_IN * DIM;

    __nv_bfloat16* xbf = nullptr; __nv_bfloat16* wbf = nullptr;
    float* ga = nullptr; float* gb = nullptr;
    cudaGetSymbolAddress((void**)&xbf, g_Xbf);
    cudaGetSymbolAddress((void**)&wbf, g_Wbf);
    cudaGetSymbolAddress((void**)&ga, g_A);
    cudaGetSymbolAddress((void**)&gb, g_B);

    const int SMEM_BYTES = A_BYTES + STAGES * STG_BYTES;   // 56KB
    cudaFuncSetAttribute(gemm_mma_kernel, cudaFuncAttributeMaxDynamicSharedMemorySize, SMEM_BYTES);

    init_kernel<<<(KC + 255) / 256, 256>>>();
    prep_kernel<<<N_IN / 8, 256>>>(x, xbf, ga, N_IN);
    prep_kernel<<<KC / 8, 256>>>(w, wbf, gb, KC);

    gemm_mma_kernel<<<N_IN / M_TILE, 128, SMEM_BYTES>>>(x, w, out_enc);

    epilogue_kernel<<<N_IN / 64, 256>>>(x, w, out_qst, out_enc);
    finalize_kernel<<<1, 256>>>(out_loss, out_perp);
}